// round 1
// baseline (speedup 1.0000x reference)
#include <cuda_runtime.h>
#include <math.h>

#define N_NODES 20000
#define N_EDGES 640000
#define ND 128
#define ED 64
#define HID 128
#define K1 (2*ND+ED)   // 320

// ---- scratch (device globals: no allocations allowed) ----
__device__ float g_aggr[(size_t)N_NODES * HID];   // segment-summed edge messages
__device__ float g_cacc[(size_t)N_NODES * 3];     // coord update accumulator

typedef unsigned long long u64;

__device__ __forceinline__ float silu_f(float x){ return x / (1.0f + __expf(-x)); }
__device__ __forceinline__ u64 splat2(float a){ u64 r; asm("mov.b64 %0, {%1, %1};" : "=l"(r) : "f"(a)); return r; }
__device__ __forceinline__ u64 pack2(float lo, float hi){ u64 r; asm("mov.b64 %0, {%1, %2};" : "=l"(r) : "f"(lo), "f"(hi)); return r; }
__device__ __forceinline__ void fma2(u64& d, u64 a, u64 b){ asm("fma.rn.f32x2 %0, %1, %2, %3;" : "=l"(d) : "l"(a), "l"(b), "l"(d)); }
__device__ __forceinline__ float2 unpack2(u64 v){ float2 f; asm("mov.b64 {%0, %1}, %2;" : "=f"(f.x), "=f"(f.y) : "l"(v)); return f; }

// ------------------------------------------------------------------
// zero scratch before each replay
// ------------------------------------------------------------------
__global__ void zero_kernel()
{
    const int total = N_NODES * HID + N_NODES * 3;
    int i = blockIdx.x * blockDim.x + threadIdx.x;
    if (i < total) {
        if (i < N_NODES * HID) g_aggr[i] = 0.0f;
        else                   g_cacc[i - N_NODES * HID] = 0.0f;
    }
}

// ------------------------------------------------------------------
// Edge kernel: fused gather -> edge MLP -> scatter(msg) -> coord MLP -> scatter(coord)
// Tile: 128 edges x 128 hid per block, 256 threads,
// micro-tile 8 edges x 8 cols per thread (packed f32x2 over column pairs).
// ------------------------------------------------------------------
#define TILE_E 128
#define KC 32
#define KC_PAD 36

struct __align__(16) EdgeSmem {
    float As[2][TILE_E][KC_PAD];  // gathered edge_feat chunks   (36 KB)
    float Bs[2][KC][HID];         // weight chunks; reused for cW1 (32 KB)
    float Hs[TILE_E][HID + 4];    // h1 then edge_message        (67.6 KB)
    int   src[TILE_E];
    int   dst[TILE_E];
    float eb1[HID];
    float eb2[HID];
    float cb1[64];
    float cw2[64];
    float cb2;
};

__global__ __launch_bounds__(256, 1)
void edge_kernel(const float* __restrict__ node_feat,
                 const int*   __restrict__ edge_index,
                 const float* __restrict__ edge_attr,
                 const float* __restrict__ coords,
                 const float* __restrict__ eW1, const float* __restrict__ eb1,
                 const float* __restrict__ eW2, const float* __restrict__ eb2,
                 const float* __restrict__ cW1, const float* __restrict__ cb1,
                 const float* __restrict__ cW2, const float* __restrict__ cb2)
{
    extern __shared__ char smem_raw[];
    EdgeSmem& sm = *reinterpret_cast<EdgeSmem*>(smem_raw);

    const int tid = threadIdx.x;
    const int tx = tid & 15;        // column group: cols tx*8 .. tx*8+7
    const int ty = tid >> 4;        // edge group:   edges ty*8 .. ty*8+7
    const int e0 = blockIdx.x * TILE_E;

    if (tid < TILE_E) {
        sm.src[tid] = edge_index[e0 + tid];
        sm.dst[tid] = edge_index[N_EDGES + e0 + tid];
        sm.eb1[tid] = eb1[tid];
        sm.eb2[tid] = eb2[tid];
        if (tid < 64) { sm.cb1[tid] = cb1[tid]; sm.cw2[tid] = cW2[tid]; }
        if (tid == 0) sm.cb2 = cb2[0];
    }
    __syncthreads();

    // ---- staging helpers ----
    const int se = tid >> 1;   // A-staging: edge index
    const int sh = tid & 1;    // which 16-float half of the 32-wide chunk
    float4 ra[4];
    auto ldA = [&](int kb) {
        const int kg = kb + sh * 16;
        const float* p;
        if (kg < ND)          p = node_feat + (size_t)sm.src[se] * ND + kg;
        else if (kg < 2*ND)   p = node_feat + (size_t)sm.dst[se] * ND + (kg - ND);
        else                  p = edge_attr + (size_t)(e0 + se) * ED + (kg - 2*ND);
        ra[0] = *(const float4*)(p);
        ra[1] = *(const float4*)(p + 4);
        ra[2] = *(const float4*)(p + 8);
        ra[3] = *(const float4*)(p + 12);
    };
    auto stA = [&](int buf) {
        float* q = &sm.As[buf][se][sh * 16];
        *(float4*)(q)      = ra[0];
        *(float4*)(q + 4)  = ra[1];
        *(float4*)(q + 8)  = ra[2];
        *(float4*)(q + 12) = ra[3];
    };
    float4 rb[4];
    auto ldB = [&](const float* W, int kb) {
        #pragma unroll
        for (int r = 0; r < 4; r++) {
            const int f = tid + r * 256;
            const int k = f >> 5, n4 = f & 31;
            rb[r] = *(const float4*)(W + (size_t)(kb + k) * HID + n4 * 4);
        }
    };
    auto stB = [&](int buf) {
        #pragma unroll
        for (int r = 0; r < 4; r++) {
            const int f = tid + r * 256;
            const int k = f >> 5, n4 = f & 31;
            *(float4*)(&sm.Bs[buf][k][n4 * 4]) = rb[r];
        }
    };

    // =========================== GEMM1: [128,320]@[320,128] ===========================
    u64 acc[8][4];
    #pragma unroll
    for (int i = 0; i < 8; i++)
        #pragma unroll
        for (int j = 0; j < 4; j++) acc[i][j] = 0ull;

    ldA(0); ldB(eW1, 0); stA(0); stB(0);
    __syncthreads();

    const int NC1 = K1 / KC;   // 10
    for (int c = 0; c < NC1; ++c) {
        const int cur = c & 1;
        if (c + 1 < NC1) { ldA((c + 1) * KC); ldB(eW1, (c + 1) * KC); }
        #pragma unroll 4
        for (int kk = 0; kk < KC; ++kk) {
            ulonglong2 b01 = *(const ulonglong2*)&sm.Bs[cur][kk][tx * 8];
            ulonglong2 b23 = *(const ulonglong2*)&sm.Bs[cur][kk][tx * 8 + 4];
            #pragma unroll
            for (int i = 0; i < 8; i++) {
                u64 ap = splat2(sm.As[cur][ty * 8 + i][kk]);
                fma2(acc[i][0], ap, b01.x);
                fma2(acc[i][1], ap, b01.y);
                fma2(acc[i][2], ap, b23.x);
                fma2(acc[i][3], ap, b23.y);
            }
        }
        if (c + 1 < NC1) { const int nxt = (c + 1) & 1; stA(nxt); stB(nxt); }
        __syncthreads();
    }

    // bias + SiLU -> Hs (h1)
    #pragma unroll
    for (int i = 0; i < 8; i++) {
        const int e = ty * 8 + i;
        #pragma unroll
        for (int j = 0; j < 4; j++) {
            const int n = tx * 8 + j * 2;
            float2 v = unpack2(acc[i][j]);
            v.x = silu_f(v.x + sm.eb1[n]);
            v.y = silu_f(v.y + sm.eb1[n + 1]);
            *(float2*)&sm.Hs[e][n] = v;
        }
    }

    // =========================== GEMM2: [128,128]@[128,128] ===========================
    u64 acc2[8][4];
    #pragma unroll
    for (int i = 0; i < 8; i++)
        #pragma unroll
        for (int j = 0; j < 4; j++) acc2[i][j] = 0ull;

    ldB(eW2, 0); stB(0);
    __syncthreads();

    const int NC2 = HID / KC;  // 4
    for (int c = 0; c < NC2; ++c) {
        const int cur = c & 1;
        if (c + 1 < NC2) ldB(eW2, (c + 1) * KC);
        const int kb = c * KC;
        #pragma unroll 4
        for (int kk = 0; kk < KC; ++kk) {
            ulonglong2 b01 = *(const ulonglong2*)&sm.Bs[cur][kk][tx * 8];
            ulonglong2 b23 = *(const ulonglong2*)&sm.Bs[cur][kk][tx * 8 + 4];
            #pragma unroll
            for (int i = 0; i < 8; i++) {
                u64 ap = splat2(sm.Hs[ty * 8 + i][kb + kk]);
                fma2(acc2[i][0], ap, b01.x);
                fma2(acc2[i][1], ap, b01.y);
                fma2(acc2[i][2], ap, b23.x);
                fma2(acc2[i][3], ap, b23.y);
            }
        }
        if (c + 1 < NC2) { const int nxt = (c + 1) & 1; stB(nxt); }
        __syncthreads();
    }

    // bias + SiLU -> edge_message; scatter atomics + store to Hs (overwrite h1)
    float2 msg2[8][4];
    #pragma unroll
    for (int i = 0; i < 8; i++) {
        #pragma unroll
        for (int j = 0; j < 4; j++) {
            const int n = tx * 8 + j * 2;
            float2 v = unpack2(acc2[i][j]);
            v.x = silu_f(v.x + sm.eb2[n]);
            v.y = silu_f(v.y + sm.eb2[n + 1]);
            msg2[i][j] = v;
        }
    }
    #pragma unroll
    for (int i = 0; i < 8; i++) {
        const int e = ty * 8 + i;
        float* ag = g_aggr + (size_t)sm.dst[e] * HID + tx * 8;
        #pragma unroll
        for (int j = 0; j < 4; j++) {
            atomicAdd(ag + j * 2,     msg2[i][j].x);
            atomicAdd(ag + j * 2 + 1, msg2[i][j].y);
            *(float2*)&sm.Hs[e][tx * 8 + j * 2] = msg2[i][j];
        }
    }

    // stage cW1 [128,64] into the (now free) Bs region
    float* cw1s = &sm.Bs[0][0][0];  // 8192 floats = exactly 2*KC*HID
    #pragma unroll
    for (int r = 0; r < 8; r++) {
        const int f4 = tid + r * 256;
        *(float4*)(cw1s + f4 * 4) = *(const float4*)(cW1 + f4 * 4);
    }
    __syncthreads();

    // =========================== coord MLP + scatter ===========================
    // thread pair per edge: half handles 32 of the 64 hidden units
    {
        const int e = tid >> 1;
        const int half = tid & 1;
        u64 s[16];
        #pragma unroll
        for (int q = 0; q < 16; q++)
            s[q] = pack2(sm.cb1[half * 32 + 2 * q], sm.cb1[half * 32 + 2 * q + 1]);

        #pragma unroll 4
        for (int k = 0; k < HID; k++) {
            u64 hp = splat2(sm.Hs[e][k]);
            const ulonglong2* row = (const ulonglong2*)(cw1s + k * 64 + half * 32);
            #pragma unroll
            for (int q = 0; q < 8; q++) {
                ulonglong2 bb = row[q];
                fma2(s[2 * q],     hp, bb.x);
                fma2(s[2 * q + 1], hp, bb.y);
            }
        }
        float p = 0.0f;
        #pragma unroll
        for (int q = 0; q < 16; q++) {
            float2 v = unpack2(s[q]);
            const int u = half * 32 + 2 * q;
            p += silu_f(v.x) * sm.cw2[u] + silu_f(v.y) * sm.cw2[u + 1];
        }
        p += __shfl_xor_sync(0xffffffffu, p, 1);
        if (half == 0) {
            const float cw = p + sm.cb2;
            const int isrc = sm.src[e], idst = sm.dst[e];
            const float dx = coords[isrc * 3 + 0] - coords[idst * 3 + 0];
            const float dy = coords[isrc * 3 + 1] - coords[idst * 3 + 1];
            const float dz = coords[isrc * 3 + 2] - coords[idst * 3 + 2];
            const float nrm = sqrtf(dx * dx + dy * dy + dz * dz) + 1e-8f;
            const float w = cw / nrm;
            atomicAdd(&g_cacc[idst * 3 + 0], dx * w);
            atomicAdd(&g_cacc[idst * 3 + 1], dy * w);
            atomicAdd(&g_cacc[idst * 3 + 2], dz * w);
        }
    }
}

// ------------------------------------------------------------------
// Node kernel: node MLP (residual) + coord finalize
// Tile: 64 nodes x 128 cols, 256 threads, micro 4x8.
// ------------------------------------------------------------------
#define TILE_N 64

struct __align__(16) NodeSmem {
    float As[2][TILE_N][KC_PAD];  // 18 KB
    float Bs[2][KC][HID];         // 32 KB
    float Hs[TILE_N][HID + 4];    // 33.8 KB
    float nb1[HID];
    float nb2[HID];
};

__global__ __launch_bounds__(256, 1)
void node_kernel(const float* __restrict__ node_feat,
                 const float* __restrict__ coords,
                 const float* __restrict__ nW1, const float* __restrict__ nb1,
                 const float* __restrict__ nW2, const float* __restrict__ nb2,
                 float* __restrict__ out)
{
    extern __shared__ char smem_raw[];
    NodeSmem& sm = *reinterpret_cast<NodeSmem*>(smem_raw);

    const int tid = threadIdx.x;
    const int tx = tid & 15;
    const int ty = tid >> 4;
    const int n0 = blockIdx.x * TILE_N;

    if (tid < HID) { sm.nb1[tid] = nb1[tid]; sm.nb2[tid] = nb2[tid]; }
    __syncthreads();

    const int se = tid >> 2;    // node row for A-staging (0..63)
    const int sq = tid & 3;     // 8-float quarter of the 32-chunk
    float4 ra[2];
    auto ldA = [&](int kb) {
        const int kg = kb + sq * 8;
        const int node = min(n0 + se, N_NODES - 1);
        const float* p = (kg < ND) ? node_feat + (size_t)node * ND + kg
                                   : g_aggr + (size_t)node * HID + (kg - ND);
        ra[0] = *(const float4*)(p);
        ra[1] = *(const float4*)(p + 4);
    };
    auto stA = [&](int buf) {
        float* q = &sm.As[buf][se][sq * 8];
        *(float4*)(q)     = ra[0];
        *(float4*)(q + 4) = ra[1];
    };
    float4 rb[4];
    auto ldB = [&](const float* W, int kb) {
        #pragma unroll
        for (int r = 0; r < 4; r++) {
            const int f = tid + r * 256;
            const int k = f >> 5, n4 = f & 31;
            rb[r] = *(const float4*)(W + (size_t)(kb + k) * HID + n4 * 4);
        }
    };
    auto stB = [&](int buf) {
        #pragma unroll
        for (int r = 0; r < 4; r++) {
            const int f = tid + r * 256;
            const int k = f >> 5, n4 = f & 31;
            *(float4*)(&sm.Bs[buf][k][n4 * 4]) = rb[r];
        }
    };

    // ---- GEMM1: [64,256]@[256,128] ----
    u64 acc[4][4];
    #pragma unroll
    for (int i = 0; i < 4; i++)
        #pragma unroll
        for (int j = 0; j < 4; j++) acc[i][j] = 0ull;

    ldA(0); ldB(nW1, 0); stA(0); stB(0);
    __syncthreads();

    const int NC1 = (ND + HID) / KC;  // 8
    for (int c = 0; c < NC1; ++c) {
        const int cur = c & 1;
        if (c + 1 < NC1) { ldA((c + 1) * KC); ldB(nW1, (c + 1) * KC); }
        #pragma unroll 4
        for (int kk = 0; kk < KC; ++kk) {
            ulonglong2 b01 = *(const ulonglong2*)&sm.Bs[cur][kk][tx * 8];
            ulonglong2 b23 = *(const ulonglong2*)&sm.Bs[cur][kk][tx * 8 + 4];
            #pragma unroll
            for (int i = 0; i < 4; i++) {
                u64 ap = splat2(sm.As[cur][ty * 4 + i][kk]);
                fma2(acc[i][0], ap, b01.x);
                fma2(acc[i][1], ap, b01.y);
                fma2(acc[i][2], ap, b23.x);
                fma2(acc[i][3], ap, b23.y);
            }
        }
        if (c + 1 < NC1) { const int nxt = (c + 1) & 1; stA(nxt); stB(nxt); }
        __syncthreads();
    }

    #pragma unroll
    for (int i = 0; i < 4; i++) {
        const int e = ty * 4 + i;
        #pragma unroll
        for (int j = 0; j < 4; j++) {
            const int n = tx * 8 + j * 2;
            float2 v = unpack2(acc[i][j]);
            v.x = silu_f(v.x + sm.nb1[n]);
            v.y = silu_f(v.y + sm.nb1[n + 1]);
            *(float2*)&sm.Hs[e][n] = v;
        }
    }

    // ---- GEMM2: [64,128]@[128,128] ----
    u64 acc2[4][4];
    #pragma unroll
    for (int i = 0; i < 4; i++)
        #pragma unroll
        for (int j = 0; j < 4; j++) acc2[i][j] = 0ull;

    ldB(nW2, 0); stB(0);
    __syncthreads();

    const int NC2 = HID / KC;  // 4
    for (int c = 0; c < NC2; ++c) {
        const int cur = c & 1;
        if (c + 1 < NC2) ldB(nW2, (c + 1) * KC);
        const int kb = c * KC;
        #pragma unroll 4
        for (int kk = 0; kk < KC; ++kk) {
            ulonglong2 b01 = *(const ulonglong2*)&sm.Bs[cur][kk][tx * 8];
            ulonglong2 b23 = *(const ulonglong2*)&sm.Bs[cur][kk][tx * 8 + 4];
            #pragma unroll
            for (int i = 0; i < 4; i++) {
                u64 ap = splat2(sm.Hs[ty * 4 + i][kb + kk]);
                fma2(acc2[i][0], ap, b01.x);
                fma2(acc2[i][1], ap, b01.y);
                fma2(acc2[i][2], ap, b23.x);
                fma2(acc2[i][3], ap, b23.y);
            }
        }
        if (c + 1 < NC2) { const int nxt = (c + 1) & 1; stB(nxt); }
        __syncthreads();
    }

    // residual output
    #pragma unroll
    for (int i = 0; i < 4; i++) {
        const int node = n0 + ty * 4 + i;
        if (node < N_NODES) {
            #pragma unroll
            for (int j = 0; j < 4; j++) {
                const int n = tx * 8 + j * 2;
                float2 v = unpack2(acc2[i][j]);
                out[(size_t)node * ND + n]     = v.x + sm.nb2[n]     + node_feat[(size_t)node * ND + n];
                out[(size_t)node * ND + n + 1] = v.y + sm.nb2[n + 1] + node_feat[(size_t)node * ND + n + 1];
            }
        }
    }

    // coord finalize
    for (int idx = tid; idx < TILE_N * 3; idx += 256) {
        const int node = n0 + idx / 3;
        const int c = idx % 3;
        if (node < N_NODES)
            out[(size_t)N_NODES * ND + node * 3 + c] = coords[node * 3 + c] + g_cacc[node * 3 + c];
    }
}

// ------------------------------------------------------------------
extern "C" void kernel_launch(void* const* d_in, const int* in_sizes, int n_in,
                              void* d_out, int out_size)
{
    const float* node_feat  = (const float*)d_in[0];
    const int*   edge_index = (const int*)  d_in[1];
    const float* edge_attr  = (const float*)d_in[2];
    const float* coords     = (const float*)d_in[3];
    const float* eW1 = (const float*)d_in[4];
    const float* eb1 = (const float*)d_in[5];
    const float* eW2 = (const float*)d_in[6];
    const float* eb2 = (const float*)d_in[7];
    const float* nW1 = (const float*)d_in[8];
    const float* nb1 = (const float*)d_in[9];
    const float* nW2 = (const float*)d_in[10];
    const float* nb2 = (const float*)d_in[11];
    const float* cW1 = (const float*)d_in[12];
    const float* cb1 = (const float*)d_in[13];
    const float* cW2 = (const float*)d_in[14];
    const float* cb2 = (const float*)d_in[15];
    float* out = (float*)d_out;

    cudaFuncSetAttribute(edge_kernel, cudaFuncAttributeMaxDynamicSharedMemorySize, (int)sizeof(EdgeSmem));
    cudaFuncSetAttribute(node_kernel, cudaFuncAttributeMaxDynamicSharedMemorySize, (int)sizeof(NodeSmem));

    const int ztotal = N_NODES * HID + N_NODES * 3;
    zero_kernel<<<(ztotal + 255) / 256, 256>>>();

    edge_kernel<<<N_EDGES / TILE_E, 256, sizeof(EdgeSmem)>>>(
        node_feat, edge_index, edge_attr, coords,
        eW1, eb1, eW2, eb2, cW1, cb1, cW2, cb2);

    node_kernel<<<(N_NODES + TILE_N - 1) / TILE_N, 256, sizeof(NodeSmem)>>>(
        node_feat, coords, nW1, nb1, nW2, nb2, out);
}